// round 2
// baseline (speedup 1.0000x reference)
#include <cuda_runtime.h>

// Problem dims
#define SDIM 1024
#define NB   8
#define DDIM 1024
#define HH   16
#define DKH  64

// ---------------- scratch (device globals; no allocations allowed) ----------
__device__ float g_Qp[(size_t)NB * HH * SDIM * DKH];   // [N,H,S,DK]
__device__ float g_Qs[(size_t)NB * HH * SDIM * DKH];
__device__ float g_Kh[(size_t)NB * HH * SDIM * DKH];
__device__ float g_Vh[(size_t)NB * HH * SDIM * DKH];
__device__ float g_ctx0[(size_t)NB * SDIM * DDIM];     // [N,S,D]
__device__ float g_ctx1[(size_t)NB * SDIM * DDIM];
__device__ float g_madd[(size_t)NB * SDIM];            // 0 or -1e9 additive mask

// ---------------- mask canonicalization -------------------------------------
// The key_padding_mask is bool in the reference; the harness may hand it to us
// as uint8, int32, or float32. Detect the element width from the byte pattern
// (within the first NB*SDIM bytes, safe for all widths), then expand to fp32
// additive form.
__global__ void mask_expand_kernel(const unsigned char* __restrict__ m,
                                   float* __restrict__ madd)
{
    __shared__ int s_big, s_nonmult4, s_anynz;
    const int t = threadIdx.x;               // 1024 threads, single block
    if (t == 0) { s_big = 0; s_nonmult4 = 0; s_anynz = 0; }
    __syncthreads();

    const int total = NB * SDIM;             // 8192 entries (and >= 8192 bytes)
    int big = 0, nonm4 = 0, anynz = 0;
    for (int i = t; i < total; i += 1024) {
        unsigned char b = m[i];
        if (b > 1) big = 1;
        if (b) { anynz = 1; if (i & 3) nonm4 = 1; }
    }
    if (big)   atomicOr(&s_big, 1);
    if (nonm4) atomicOr(&s_nonmult4, 1);
    if (anynz) atomicOr(&s_anynz, 1);
    __syncthreads();

    // width4 if: floats present (bytes>1), or all nonzeros sit at 4-byte
    // boundaries (int32 bools), or no nonzero at all in the 1-byte window.
    const bool width4 = s_big || !s_nonmult4 || !s_anynz;

    for (int i = t; i < total; i += 1024) {
        unsigned char v;
        if (width4) {
            v = (unsigned char)(m[4 * i] | m[4 * i + 1] | m[4 * i + 2] | m[4 * i + 3]);
        } else {
            v = m[i];
        }
        madd[i] = v ? -1e9f : 0.f;
    }
}

// ---------------- GEMM: C[m,dout] = sum_k A[m,k] * W[dout,k] + b[dout] ------
// MODE 0: projection.  A rows m = s*NB+n (X is [S,N,D]); out -> [N,H,S,DK]
// MODE 1: output FC.   A rows m = n*SDIM+s (ctx is [N,S,D]); out -> [S,N,D]
template <int MODE>
__global__ void __launch_bounds__(256)
gemm_kernel(const float* __restrict__ A, const float* __restrict__ W,
            const float* __restrict__ bias, float* __restrict__ out)
{
    constexpr int BM = 64, BN = 64, BK = 16, KD = 1024;
    __shared__ float As[BK][BM + 4];
    __shared__ float Bs[BK][BN + 4];

    const int tid = threadIdx.x;
    const int tx = tid & 15;        // 0..15 -> output cols
    const int ty = tid >> 4;        // 0..15 -> output rows
    const int m0 = blockIdx.y * BM;
    const int n0 = blockIdx.x * BN;

    const int lrow = tid >> 2;          // 0..63
    const int lcol = (tid & 3) << 2;    // 0,4,8,12

    float c[4][4] = {};

    for (int k0 = 0; k0 < KD; k0 += BK) {
        float4 a4 = *(const float4*)(A + (size_t)(m0 + lrow) * KD + k0 + lcol);
        float4 b4 = *(const float4*)(W + (size_t)(n0 + lrow) * KD + k0 + lcol);
        As[lcol + 0][lrow] = a4.x; As[lcol + 1][lrow] = a4.y;
        As[lcol + 2][lrow] = a4.z; As[lcol + 3][lrow] = a4.w;
        Bs[lcol + 0][lrow] = b4.x; Bs[lcol + 1][lrow] = b4.y;
        Bs[lcol + 2][lrow] = b4.z; Bs[lcol + 3][lrow] = b4.w;
        __syncthreads();

        #pragma unroll
        for (int kk = 0; kk < BK; kk++) {
            float4 av = *(const float4*)(&As[kk][ty << 2]);
            float4 bv = *(const float4*)(&Bs[kk][tx << 2]);
            float ar[4] = {av.x, av.y, av.z, av.w};
            float br[4] = {bv.x, bv.y, bv.z, bv.w};
            #pragma unroll
            for (int i = 0; i < 4; i++)
                #pragma unroll
                for (int j = 0; j < 4; j++)
                    c[i][j] += ar[i] * br[j];
        }
        __syncthreads();
    }

    float4 bv4 = *(const float4*)(bias + n0 + (tx << 2));
    const float bb[4] = {bv4.x, bv4.y, bv4.z, bv4.w};
    const int dout = n0 + (tx << 2);

    #pragma unroll
    for (int i = 0; i < 4; i++) {
        const int m = m0 + (ty << 2) + i;
        float4 v;
        v.x = c[i][0] + bb[0];
        v.y = c[i][1] + bb[1];
        v.z = c[i][2] + bb[2];
        v.w = c[i][3] + bb[3];
        if (MODE == 0) {
            const int s = m >> 3, n = m & 7;          // m = s*NB + n
            const int h = dout >> 6, dk = dout & 63;  // dout = h*DK + dk
            *(float4*)(out + ((size_t)((n * HH + h) * SDIM + s)) * DKH + dk) = v;
        } else {
            const int n = m >> 10, s = m & 1023;      // m = n*SDIM + s
            *(float4*)(out + ((size_t)(s * NB + n)) * DDIM + dout) = v;
        }
    }
}

// ---------------- attention: flash-style, 1 thread = 1 query row ------------
// grid: (S/QT, N*H, 2 streams), block: QT=128 threads
// smem: K tile [64][64], V tile [64][64], scores [128][65], mask-add [64]
#define QT 128
#define KT 64

__global__ void __launch_bounds__(QT)
attn_kernel(const float* __restrict__ Qp, const float* __restrict__ Qs,
            const float* __restrict__ Kh, const float* __restrict__ Vh,
            const float* __restrict__ maddg,
            float* __restrict__ ctx0, float* __restrict__ ctx1)
{
    extern __shared__ float sm[];
    float* Ks   = sm;                       // KT*DKH
    float* Vs   = Ks + KT * DKH;            // KT*DKH
    float* Ss   = Vs + KT * DKH;            // QT*(KT+1)
    float* madd = Ss + QT * (KT + 1);       // KT

    const int q0 = blockIdx.x * QT;
    const int nh = blockIdx.y;              // n*H + h
    const int n  = nh / HH;
    const int stream = blockIdx.z;
    const int t = threadIdx.x;
    const int q = q0 + t;

    const float* Qbase = (stream ? Qs : Qp) + (size_t)nh * SDIM * DKH;
    const float* Kb = Kh + (size_t)nh * SDIM * DKH;
    const float* Vb = Vh + (size_t)nh * SDIM * DKH;

    float qv[DKH];
    {
        const float4* qrow = (const float4*)(Qbase + (size_t)q * DKH);
        #pragma unroll
        for (int d4 = 0; d4 < DKH / 4; d4++) {
            float4 v = qrow[d4];
            qv[4 * d4 + 0] = v.x; qv[4 * d4 + 1] = v.y;
            qv[4 * d4 + 2] = v.z; qv[4 * d4 + 3] = v.w;
        }
    }

    float acc[DKH];
    #pragma unroll
    for (int d = 0; d < DKH; d++) acc[d] = 0.f;
    float m_i = -1e30f, l_i = 0.f;

    for (int kt = 0; kt < SDIM / KT; kt++) {
        const int k0 = kt * KT;
        // cooperative tile loads: 1024 float4 each, 8 per thread
        const float4* ksrc = (const float4*)(Kb + (size_t)k0 * DKH);
        const float4* vsrc = (const float4*)(Vb + (size_t)k0 * DKH);
        float4* kd = (float4*)Ks;
        float4* vd = (float4*)Vs;
        #pragma unroll
        for (int i = 0; i < (KT * DKH / 4) / QT; i++) {
            kd[t + QT * i] = ksrc[t + QT * i];
            vd[t + QT * i] = vsrc[t + QT * i];
        }
        if (t < KT) madd[t] = maddg[n * SDIM + k0 + t];
        __syncthreads();

        // pass 1: scores for this thread's query vs 64 keys
        float tmax = -1e30f;
        for (int j = 0; j < KT; j++) {
            const float4* krow = (const float4*)(Ks + j * DKH);
            float s = 0.f;
            #pragma unroll
            for (int d4 = 0; d4 < DKH / 4; d4++) {
                float4 kk = krow[d4];
                s += qv[4 * d4 + 0] * kk.x + qv[4 * d4 + 1] * kk.y
                   + qv[4 * d4 + 2] * kk.z + qv[4 * d4 + 3] * kk.w;
            }
            s = s * 0.125f + madd[j];   // 1/sqrt(64) = 0.125
            Ss[t * (KT + 1) + j] = s;
            tmax = fmaxf(tmax, s);
        }

        const float m_new = fmaxf(m_i, tmax);
        const float corr = __expf(m_i - m_new);
        l_i *= corr;
        #pragma unroll
        for (int d = 0; d < DKH; d++) acc[d] *= corr;

        // pass 2: accumulate P@V
        for (int j = 0; j < KT; j++) {
            const float p = __expf(Ss[t * (KT + 1) + j] - m_new);
            l_i += p;
            const float4* vrow = (const float4*)(Vs + j * DKH);
            #pragma unroll
            for (int d4 = 0; d4 < DKH / 4; d4++) {
                float4 vv = vrow[d4];
                acc[4 * d4 + 0] += p * vv.x;
                acc[4 * d4 + 1] += p * vv.y;
                acc[4 * d4 + 2] += p * vv.z;
                acc[4 * d4 + 3] += p * vv.w;
            }
        }
        m_i = m_new;
        __syncthreads();
    }

    const float inv = 1.f / l_i;
    float* outp = (stream ? ctx1 : ctx0) + ((size_t)(n * SDIM + q)) * DDIM + (nh % HH) * DKH;
    #pragma unroll
    for (int d4 = 0; d4 < DKH / 4; d4++) {
        float4 v;
        v.x = acc[4 * d4 + 0] * inv;
        v.y = acc[4 * d4 + 1] * inv;
        v.z = acc[4 * d4 + 2] * inv;
        v.w = acc[4 * d4 + 3] * inv;
        *(float4*)(outp + 4 * d4) = v;
    }
}

// ---------------------------------------------------------------------------
extern "C" void kernel_launch(void* const* d_in, const int* in_sizes, int n_in,
                              void* d_out, int out_size)
{
    const float* Qpoi = (const float*)d_in[0];
    const float* Qsvi = (const float*)d_in[1];
    const float* Kin  = (const float*)d_in[2];
    const float* Vin  = (const float*)d_in[3];
    const unsigned char* mask = (const unsigned char*)d_in[4];
    const float* wq_poi_w = (const float*)d_in[5];
    const float* wq_poi_b = (const float*)d_in[6];
    const float* wq_svi_w = (const float*)d_in[7];
    const float* wq_svi_b = (const float*)d_in[8];
    const float* wk_w = (const float*)d_in[9];
    const float* wk_b = (const float*)d_in[10];
    const float* wv_w = (const float*)d_in[11];
    const float* wv_b = (const float*)d_in[12];
    const float* fc_w = (const float*)d_in[13];
    const float* fc_b = (const float*)d_in[14];
    float* out = (float*)d_out;

    float *Qp, *Qs, *Kh, *Vh, *c0, *c1, *madd;
    cudaGetSymbolAddress((void**)&Qp, g_Qp);
    cudaGetSymbolAddress((void**)&Qs, g_Qs);
    cudaGetSymbolAddress((void**)&Kh, g_Kh);
    cudaGetSymbolAddress((void**)&Vh, g_Vh);
    cudaGetSymbolAddress((void**)&c0, g_ctx0);
    cudaGetSymbolAddress((void**)&c1, g_ctx1);
    cudaGetSymbolAddress((void**)&madd, g_madd);

    // 0) canonicalize padding mask (handles uint8 / int32 / float32 storage)
    mask_expand_kernel<<<1, 1024>>>(mask, madd);

    dim3 gg(DDIM / 64, (SDIM * NB) / 64);   // 16 x 128 tiles

    // 1) projections -> [N,H,S,DK]
    gemm_kernel<0><<<gg, 256>>>(Qpoi, wq_poi_w, wq_poi_b, Qp);
    gemm_kernel<0><<<gg, 256>>>(Qsvi, wq_svi_w, wq_svi_b, Qs);
    gemm_kernel<0><<<gg, 256>>>(Kin,  wk_w,     wk_b,     Kh);
    gemm_kernel<0><<<gg, 256>>>(Vin,  wv_w,     wv_b,     Vh);

    // 2) attention (both streams in z)
    const int smem = (KT * DKH + KT * DKH + QT * (KT + 1) + KT) * (int)sizeof(float);
    cudaFuncSetAttribute((const void*)attn_kernel,
                         cudaFuncAttributeMaxDynamicSharedMemorySize, smem);
    attn_kernel<<<dim3(SDIM / QT, NB * HH, 2), QT, smem>>>(Qp, Qs, Kh, Vh, madd, c0, c1);

    // 3) output FC -> [S,N,D], poi then svi
    gemm_kernel<1><<<gg, 256>>>(c0, fc_w, fc_b, out);
    gemm_kernel<1><<<gg, 256>>>(c1, fc_w, fc_b, out + (size_t)SDIM * NB * DDIM);
}

// round 3
// speedup vs baseline: 1.5546x; 1.5546x over previous
#include <cuda_runtime.h>
#include <cstdint>

// Problem dims
#define SDIM 1024
#define NB   8
#define DDIM 1024
#define HH   16
#define DKH  64

// ---------------- scratch (device globals; no allocations allowed) ----------
__device__ float g_Qp[(size_t)NB * HH * SDIM * DKH];   // [N,H,S,DK]
__device__ float g_Qs[(size_t)NB * HH * SDIM * DKH];
__device__ float g_Kh[(size_t)NB * HH * SDIM * DKH];
__device__ float g_Vh[(size_t)NB * HH * SDIM * DKH];
__device__ float g_ctx0[(size_t)NB * SDIM * DDIM];     // [N,S,D]
__device__ float g_ctx1[(size_t)NB * SDIM * DDIM];
__device__ float g_madd[(size_t)NB * SDIM];            // 0 or -1e9 additive mask

// ---------------- mask canonicalization -------------------------------------
__global__ void mask_expand_kernel(const unsigned char* __restrict__ m,
                                   float* __restrict__ madd)
{
    __shared__ int s_big, s_nonmult4, s_anynz;
    const int t = threadIdx.x;               // 1024 threads, single block
    if (t == 0) { s_big = 0; s_nonmult4 = 0; s_anynz = 0; }
    __syncthreads();

    const int total = NB * SDIM;             // 8192 entries
    int big = 0, nonm4 = 0, anynz = 0;
    for (int i = t; i < total; i += 1024) {
        unsigned char b = m[i];
        if (b > 1) big = 1;
        if (b) { anynz = 1; if (i & 3) nonm4 = 1; }
    }
    if (big)   atomicOr(&s_big, 1);
    if (nonm4) atomicOr(&s_nonmult4, 1);
    if (anynz) atomicOr(&s_anynz, 1);
    __syncthreads();

    const bool width4 = s_big || !s_nonmult4 || !s_anynz;

    for (int i = t; i < total; i += 1024) {
        unsigned char v;
        if (width4) {
            v = (unsigned char)(m[4 * i] | m[4 * i + 1] | m[4 * i + 2] | m[4 * i + 3]);
        } else {
            v = m[i];
        }
        madd[i] = v ? -1e9f : 0.f;
    }
}

// ---------------- tf32 mma helpers ------------------------------------------
__device__ __forceinline__ float to_tf32(float x) {
    float r;
    asm("cvt.rna.tf32.f32 %0, %1;" : "=f"(r) : "f"(x));
    return r;
}

__device__ __forceinline__ void mma_tf32_16x8x8(float* c, const uint32_t* a,
                                                const uint32_t* b)
{
    asm volatile(
        "mma.sync.aligned.m16n8k8.row.col.f32.tf32.tf32.f32 "
        "{%0,%1,%2,%3}, {%4,%5,%6,%7}, {%8,%9}, {%0,%1,%2,%3};"
        : "+f"(c[0]), "+f"(c[1]), "+f"(c[2]), "+f"(c[3])
        : "r"(a[0]), "r"(a[1]), "r"(a[2]), "r"(a[3]), "r"(b[0]), "r"(b[1]));
}

// ---------------- tensor-core GEMM ------------------------------------------
// C[m,dout] = sum_k A[m,k] * W[dout,k] + b[dout], M=8192, N=K=1024.
// Block tile 128x128x16, 8 warps, warp tile 64x32 (4 m16 x 4 n8 mma tiles).
// MODE 0: projection.  A rows m = s*NB+n; out -> [N,H,S,DK]
// MODE 1: output FC.   A rows m = n*SDIM+s; out -> [S,N,D]
template <int MODE>
__global__ void __launch_bounds__(256)
gemm_tc(const float* __restrict__ A, const float* __restrict__ W,
        const float* __restrict__ bias, float* __restrict__ out)
{
    constexpr int BM = 128, BN = 128, BK = 16, KD = 1024;
    constexpr int STR = 20;                    // floats/row: conflict-free + 16B aligned
    __shared__ float As[BM * STR];             // [m][k]
    __shared__ float Bs[BN * STR];             // [n][k]

    const int tid  = threadIdx.x;
    const int wid  = tid >> 5;
    const int lane = tid & 31;
    const int wm = wid & 1;                    // 0..1  -> 64-row slab
    const int wn = wid >> 1;                   // 0..3  -> 32-col slab
    const int m0 = blockIdx.y * BM;
    const int n0 = blockIdx.x * BN;

    const int r  = lane >> 2;                  // fragment row 0..7
    const int cq = lane & 3;                   // fragment col quad 0..3

    float acc[4][4][4];                        // [mt][nt][reg]
    #pragma unroll
    for (int mt = 0; mt < 4; mt++)
        #pragma unroll
        for (int nt = 0; nt < 4; nt++)
            #pragma unroll
            for (int i = 0; i < 4; i++) acc[mt][nt][i] = 0.f;

    const float* Aptr = A + (size_t)m0 * KD;
    const float* Wptr = W + (size_t)n0 * KD;

    for (int k0 = 0; k0 < KD; k0 += BK) {
        // ---- global -> smem (512 float4 per operand, 2 per thread) ----
        #pragma unroll
        for (int i = 0; i < 2; i++) {
            const int idx = tid + 256 * i;
            const int row = idx >> 2;
            const int c4  = (idx & 3) << 2;
            float4 a4 = *(const float4*)(Aptr + (size_t)row * KD + k0 + c4);
            float4 b4 = *(const float4*)(Wptr + (size_t)row * KD + k0 + c4);
            float4 at, bt;
            at.x = to_tf32(a4.x); at.y = to_tf32(a4.y);
            at.z = to_tf32(a4.z); at.w = to_tf32(a4.w);
            bt.x = to_tf32(b4.x); bt.y = to_tf32(b4.y);
            bt.z = to_tf32(b4.z); bt.w = to_tf32(b4.w);
            *(float4*)(As + row * STR + c4) = at;
            *(float4*)(Bs + row * STR + c4) = bt;
        }
        __syncthreads();

        // ---- two k8 steps ----
        #pragma unroll
        for (int ks = 0; ks < 2; ks++) {
            const int kb = ks * 8;

            uint32_t af[4][4];
            #pragma unroll
            for (int mt = 0; mt < 4; mt++) {
                const int mrow = wm * 64 + mt * 16 + r;
                const float* p = As + mrow * STR + kb + cq;
                af[mt][0] = __float_as_uint(p[0]);
                af[mt][1] = __float_as_uint(p[8 * STR]);
                af[mt][2] = __float_as_uint(p[4]);
                af[mt][3] = __float_as_uint(p[8 * STR + 4]);
            }
            uint32_t bf[4][2];
            #pragma unroll
            for (int nt = 0; nt < 4; nt++) {
                const int nrow = wn * 32 + nt * 8 + r;
                const float* p = Bs + nrow * STR + kb + cq;
                bf[nt][0] = __float_as_uint(p[0]);
                bf[nt][1] = __float_as_uint(p[4]);
            }
            #pragma unroll
            for (int mt = 0; mt < 4; mt++)
                #pragma unroll
                for (int nt = 0; nt < 4; nt++)
                    mma_tf32_16x8x8(acc[mt][nt], af[mt], bf[nt]);
        }
        __syncthreads();
    }

    // ---- epilogue: bias + scatter (float2 per fragment half) ----
    const int cpair = (lane & 3) * 2;
    #pragma unroll
    for (int nt = 0; nt < 4; nt++) {
        const int dout = n0 + wn * 32 + nt * 8 + cpair;
        const float2 bb = *(const float2*)(bias + dout);
        #pragma unroll
        for (int mt = 0; mt < 4; mt++) {
            #pragma unroll
            for (int half = 0; half < 2; half++) {
                const int m = m0 + wm * 64 + mt * 16 + r + half * 8;
                float2 v;
                v.x = acc[mt][nt][half * 2 + 0] + bb.x;
                v.y = acc[mt][nt][half * 2 + 1] + bb.y;
                if (MODE == 0) {
                    const int s = m >> 3, n = m & 7;          // m = s*NB + n
                    const int h = dout >> 6, dk = dout & 63;
                    *(float2*)(out + ((size_t)((n * HH + h) * SDIM + s)) * DKH + dk) = v;
                } else {
                    const int n = m >> 10, s = m & 1023;      // m = n*SDIM + s
                    *(float2*)(out + ((size_t)(s * NB + n)) * DDIM + dout) = v;
                }
            }
        }
    }
}

// ---------------- attention: flash-style, 1 thread = 1 query row ------------
#define QT 128
#define KT 64

__global__ void __launch_bounds__(QT)
attn_kernel(const float* __restrict__ Qp, const float* __restrict__ Qs,
            const float* __restrict__ Kh, const float* __restrict__ Vh,
            const float* __restrict__ maddg,
            float* __restrict__ ctx0, float* __restrict__ ctx1)
{
    extern __shared__ float sm[];
    float* Ks   = sm;                       // KT*DKH
    float* Vs   = Ks + KT * DKH;            // KT*DKH
    float* Ss   = Vs + KT * DKH;            // QT*(KT+1)
    float* madd = Ss + QT * (KT + 1);       // KT

    const int q0 = blockIdx.x * QT;
    const int nh = blockIdx.y;              // n*H + h
    const int n  = nh / HH;
    const int stream = blockIdx.z;
    const int t = threadIdx.x;
    const int q = q0 + t;

    const float* Qbase = (stream ? Qs : Qp) + (size_t)nh * SDIM * DKH;
    const float* Kb = Kh + (size_t)nh * SDIM * DKH;
    const float* Vb = Vh + (size_t)nh * SDIM * DKH;

    float qv[DKH];
    {
        const float4* qrow = (const float4*)(Qbase + (size_t)q * DKH);
        #pragma unroll
        for (int d4 = 0; d4 < DKH / 4; d4++) {
            float4 v = qrow[d4];
            qv[4 * d4 + 0] = v.x; qv[4 * d4 + 1] = v.y;
            qv[4 * d4 + 2] = v.z; qv[4 * d4 + 3] = v.w;
        }
    }

    float acc[DKH];
    #pragma unroll
    for (int d = 0; d < DKH; d++) acc[d] = 0.f;
    float m_i = -1e30f, l_i = 0.f;

    for (int kt = 0; kt < SDIM / KT; kt++) {
        const int k0 = kt * KT;
        const float4* ksrc = (const float4*)(Kb + (size_t)k0 * DKH);
        const float4* vsrc = (const float4*)(Vb + (size_t)k0 * DKH);
        float4* kd = (float4*)Ks;
        float4* vd = (float4*)Vs;
        #pragma unroll
        for (int i = 0; i < (KT * DKH / 4) / QT; i++) {
            kd[t + QT * i] = ksrc[t + QT * i];
            vd[t + QT * i] = vsrc[t + QT * i];
        }
        if (t < KT) madd[t] = maddg[n * SDIM + k0 + t];
        __syncthreads();

        float tmax = -1e30f;
        for (int j = 0; j < KT; j++) {
            const float4* krow = (const float4*)(Ks + j * DKH);
            float s = 0.f;
            #pragma unroll
            for (int d4 = 0; d4 < DKH / 4; d4++) {
                float4 kk = krow[d4];
                s += qv[4 * d4 + 0] * kk.x + qv[4 * d4 + 1] * kk.y
                   + qv[4 * d4 + 2] * kk.z + qv[4 * d4 + 3] * kk.w;
            }
            s = s * 0.125f + madd[j];
            Ss[t * (KT + 1) + j] = s;
            tmax = fmaxf(tmax, s);
        }

        const float m_new = fmaxf(m_i, tmax);
        const float corr = __expf(m_i - m_new);
        l_i *= corr;
        #pragma unroll
        for (int d = 0; d < DKH; d++) acc[d] *= corr;

        for (int j = 0; j < KT; j++) {
            const float p = __expf(Ss[t * (KT + 1) + j] - m_new);
            l_i += p;
            const float4* vrow = (const float4*)(Vs + j * DKH);
            #pragma unroll
            for (int d4 = 0; d4 < DKH / 4; d4++) {
                float4 vv = vrow[d4];
                acc[4 * d4 + 0] += p * vv.x;
                acc[4 * d4 + 1] += p * vv.y;
                acc[4 * d4 + 2] += p * vv.z;
                acc[4 * d4 + 3] += p * vv.w;
            }
        }
        m_i = m_new;
        __syncthreads();
    }

    const float inv = 1.f / l_i;
    float* outp = (stream ? ctx1 : ctx0) + ((size_t)(n * SDIM + q)) * DDIM + (nh % HH) * DKH;
    #pragma unroll
    for (int d4 = 0; d4 < DKH / 4; d4++) {
        float4 v;
        v.x = acc[4 * d4 + 0] * inv;
        v.y = acc[4 * d4 + 1] * inv;
        v.z = acc[4 * d4 + 2] * inv;
        v.w = acc[4 * d4 + 3] * inv;
        *(float4*)(outp + 4 * d4) = v;
    }
}

// ---------------------------------------------------------------------------
extern "C" void kernel_launch(void* const* d_in, const int* in_sizes, int n_in,
                              void* d_out, int out_size)
{
    const float* Qpoi = (const float*)d_in[0];
    const float* Qsvi = (const float*)d_in[1];
    const float* Kin  = (const float*)d_in[2];
    const float* Vin  = (const float*)d_in[3];
    const unsigned char* mask = (const unsigned char*)d_in[4];
    const float* wq_poi_w = (const float*)d_in[5];
    const float* wq_poi_b = (const float*)d_in[6];
    const float* wq_svi_w = (const float*)d_in[7];
    const float* wq_svi_b = (const float*)d_in[8];
    const float* wk_w = (const float*)d_in[9];
    const float* wk_b = (const float*)d_in[10];
    const float* wv_w = (const float*)d_in[11];
    const float* wv_b = (const float*)d_in[12];
    const float* fc_w = (const float*)d_in[13];
    const float* fc_b = (const float*)d_in[14];
    float* out = (float*)d_out;

    float *Qp, *Qs, *Kh, *Vh, *c0, *c1, *madd;
    cudaGetSymbolAddress((void**)&Qp, g_Qp);
    cudaGetSymbolAddress((void**)&Qs, g_Qs);
    cudaGetSymbolAddress((void**)&Kh, g_Kh);
    cudaGetSymbolAddress((void**)&Vh, g_Vh);
    cudaGetSymbolAddress((void**)&c0, g_ctx0);
    cudaGetSymbolAddress((void**)&c1, g_ctx1);
    cudaGetSymbolAddress((void**)&madd, g_madd);

    // 0) canonicalize padding mask
    mask_expand_kernel<<<1, 1024>>>(mask, madd);

    dim3 gg(DDIM / 128, (SDIM * NB) / 128);   // 8 x 64 tiles

    // 1) projections -> [N,H,S,DK]  (tensor cores, tf32)
    gemm_tc<0><<<gg, 256>>>(Qpoi, wq_poi_w, wq_poi_b, Qp);
    gemm_tc<0><<<gg, 256>>>(Qsvi, wq_svi_w, wq_svi_b, Qs);
    gemm_tc<0><<<gg, 256>>>(Kin,  wk_w,     wk_b,     Kh);
    gemm_tc<0><<<gg, 256>>>(Vin,  wv_w,     wv_b,     Vh);

    // 2) attention (both streams in z)
    const int smem = (KT * DKH + KT * DKH + QT * (KT + 1) + KT) * (int)sizeof(float);
    cudaFuncSetAttribute((const void*)attn_kernel,
                         cudaFuncAttributeMaxDynamicSharedMemorySize, smem);
    attn_kernel<<<dim3(SDIM / QT, NB * HH, 2), QT, smem>>>(Qp, Qs, Kh, Vh, madd, c0, c1);

    // 3) output FC -> [S,N,D], poi then svi (tensor cores, tf32)
    gemm_tc<1><<<gg, 256>>>(c0, fc_w, fc_b, out);
    gemm_tc<1><<<gg, 256>>>(c1, fc_w, fc_b, out + (size_t)SDIM * NB * DDIM);
}

// round 4
// speedup vs baseline: 3.1606x; 2.0331x over previous
#include <cuda_runtime.h>
#include <cstdint>

// Problem dims
#define SDIM 1024
#define NB   8
#define DDIM 1024
#define HH   16
#define DKH  64

// ---------------- scratch (device globals; no allocations allowed) ----------
__device__ float g_Qp[(size_t)NB * HH * SDIM * DKH];   // [N,H,S,DK]
__device__ float g_Qs[(size_t)NB * HH * SDIM * DKH];
__device__ float g_Kh[(size_t)NB * HH * SDIM * DKH];
__device__ float g_Vh[(size_t)NB * HH * SDIM * DKH];
__device__ float g_ctx0[(size_t)NB * SDIM * DDIM];     // [N,S,D]
__device__ float g_ctx1[(size_t)NB * SDIM * DDIM];
__device__ float g_madd[(size_t)NB * SDIM];            // 0 or -1e9 additive mask

// ---------------- mask canonicalization -------------------------------------
__global__ void mask_expand_kernel(const unsigned char* __restrict__ m,
                                   float* __restrict__ madd)
{
    __shared__ int s_big, s_nonmult4, s_anynz;
    const int t = threadIdx.x;               // 1024 threads, single block
    if (t == 0) { s_big = 0; s_nonmult4 = 0; s_anynz = 0; }
    __syncthreads();

    const int total = NB * SDIM;             // 8192 entries
    int big = 0, nonm4 = 0, anynz = 0;
    for (int i = t; i < total; i += 1024) {
        unsigned char b = m[i];
        if (b > 1) big = 1;
        if (b) { anynz = 1; if (i & 3) nonm4 = 1; }
    }
    if (big)   atomicOr(&s_big, 1);
    if (nonm4) atomicOr(&s_nonmult4, 1);
    if (anynz) atomicOr(&s_anynz, 1);
    __syncthreads();

    const bool width4 = s_big || !s_nonmult4 || !s_anynz;

    for (int i = t; i < total; i += 1024) {
        unsigned char v;
        if (width4) {
            v = (unsigned char)(m[4 * i] | m[4 * i + 1] | m[4 * i + 2] | m[4 * i + 3]);
        } else {
            v = m[i];
        }
        madd[i] = v ? -1e9f : 0.f;
    }
}

// ---------------- tf32 mma helpers ------------------------------------------
__device__ __forceinline__ float to_tf32(float x) {
    float r;
    asm("cvt.rna.tf32.f32 %0, %1;" : "=f"(r) : "f"(x));
    return r;
}

__device__ __forceinline__ void mma_tf32_16x8x8(float* c, const uint32_t* a,
                                                const uint32_t* b)
{
    asm volatile(
        "mma.sync.aligned.m16n8k8.row.col.f32.tf32.tf32.f32 "
        "{%0,%1,%2,%3}, {%4,%5,%6,%7}, {%8,%9}, {%0,%1,%2,%3};"
        : "+f"(c[0]), "+f"(c[1]), "+f"(c[2]), "+f"(c[3])
        : "r"(a[0]), "r"(a[1]), "r"(a[2]), "r"(a[3]), "r"(b[0]), "r"(b[1]));
}

// ---------------- tensor-core GEMM ------------------------------------------
template <int MODE>
__global__ void __launch_bounds__(256)
gemm_tc(const float* __restrict__ A, const float* __restrict__ W,
        const float* __restrict__ bias, float* __restrict__ out)
{
    constexpr int BM = 128, BN = 128, BK = 16, KD = 1024;
    constexpr int STR = 20;
    __shared__ float As[BM * STR];
    __shared__ float Bs[BN * STR];

    const int tid  = threadIdx.x;
    const int wid  = tid >> 5;
    const int lane = tid & 31;
    const int wm = wid & 1;
    const int wn = wid >> 1;
    const int m0 = blockIdx.y * BM;
    const int n0 = blockIdx.x * BN;

    const int r  = lane >> 2;
    const int cq = lane & 3;

    float acc[4][4][4];
    #pragma unroll
    for (int mt = 0; mt < 4; mt++)
        #pragma unroll
        for (int nt = 0; nt < 4; nt++)
            #pragma unroll
            for (int i = 0; i < 4; i++) acc[mt][nt][i] = 0.f;

    const float* Aptr = A + (size_t)m0 * KD;
    const float* Wptr = W + (size_t)n0 * KD;

    for (int k0 = 0; k0 < KD; k0 += BK) {
        #pragma unroll
        for (int i = 0; i < 2; i++) {
            const int idx = tid + 256 * i;
            const int row = idx >> 2;
            const int c4  = (idx & 3) << 2;
            float4 a4 = *(const float4*)(Aptr + (size_t)row * KD + k0 + c4);
            float4 b4 = *(const float4*)(Wptr + (size_t)row * KD + k0 + c4);
            float4 at, bt;
            at.x = to_tf32(a4.x); at.y = to_tf32(a4.y);
            at.z = to_tf32(a4.z); at.w = to_tf32(a4.w);
            bt.x = to_tf32(b4.x); bt.y = to_tf32(b4.y);
            bt.z = to_tf32(b4.z); bt.w = to_tf32(b4.w);
            *(float4*)(As + row * STR + c4) = at;
            *(float4*)(Bs + row * STR + c4) = bt;
        }
        __syncthreads();

        #pragma unroll
        for (int ks = 0; ks < 2; ks++) {
            const int kb = ks * 8;

            uint32_t af[4][4];
            #pragma unroll
            for (int mt = 0; mt < 4; mt++) {
                const int mrow = wm * 64 + mt * 16 + r;
                const float* p = As + mrow * STR + kb + cq;
                af[mt][0] = __float_as_uint(p[0]);
                af[mt][1] = __float_as_uint(p[8 * STR]);
                af[mt][2] = __float_as_uint(p[4]);
                af[mt][3] = __float_as_uint(p[8 * STR + 4]);
            }
            uint32_t bf[4][2];
            #pragma unroll
            for (int nt = 0; nt < 4; nt++) {
                const int nrow = wn * 32 + nt * 8 + r;
                const float* p = Bs + nrow * STR + kb + cq;
                bf[nt][0] = __float_as_uint(p[0]);
                bf[nt][1] = __float_as_uint(p[4]);
            }
            #pragma unroll
            for (int mt = 0; mt < 4; mt++)
                #pragma unroll
                for (int nt = 0; nt < 4; nt++)
                    mma_tf32_16x8x8(acc[mt][nt], af[mt], bf[nt]);
        }
        __syncthreads();
    }

    const int cpair = (lane & 3) * 2;
    #pragma unroll
    for (int nt = 0; nt < 4; nt++) {
        const int dout = n0 + wn * 32 + nt * 8 + cpair;
        const float2 bb = *(const float2*)(bias + dout);
        #pragma unroll
        for (int mt = 0; mt < 4; mt++) {
            #pragma unroll
            for (int half = 0; half < 2; half++) {
                const int m = m0 + wm * 64 + mt * 16 + r + half * 8;
                float2 v;
                v.x = acc[mt][nt][half * 2 + 0] + bb.x;
                v.y = acc[mt][nt][half * 2 + 1] + bb.y;
                if (MODE == 0) {
                    const int s = m >> 3, n = m & 7;
                    const int h = dout >> 6, dk = dout & 63;
                    *(float2*)(out + ((size_t)((n * HH + h) * SDIM + s)) * DKH + dk) = v;
                } else {
                    const int n = m >> 10, s = m & 1023;
                    *(float2*)(out + ((size_t)(s * NB + n)) * DDIM + dout) = v;
                }
            }
        }
    }
}

// ---------------- tensor-core flash attention --------------------------------
// Block: 4 warps, 64 q rows (warp w owns rows w*16..+15). Loop 16 K-tiles of 64.
// QK^T and P.V via m16n8k8 tf32. Online softmax on C fragments.
#define AQT 64
#define AKT 64
#define KS_STR 68
#define VS_STR 72
#define PS_STR 68

__global__ void __launch_bounds__(128)
attn_tc(const float* __restrict__ Qp, const float* __restrict__ Qsv,
        const float* __restrict__ Kh, const float* __restrict__ Vh,
        const float* __restrict__ maddg,
        float* __restrict__ ctx0, float* __restrict__ ctx1)
{
    extern __shared__ float sm[];
    float* Ks   = sm;                         // [64][KS_STR]
    float* Vs   = Ks + AKT * KS_STR;          // [64][VS_STR]
    float* Ps   = Vs + AKT * VS_STR;          // [64][PS_STR]
    float* madd = Ps + AQT * PS_STR;          // [64]

    const int nh = blockIdx.y;
    const int n  = nh / HH;
    const int stream = blockIdx.z;
    const int q0 = blockIdx.x * AQT;
    const int tid = threadIdx.x;
    const int wid = tid >> 5;
    const int lane = tid & 31;
    const int r  = lane >> 2;
    const int cq = lane & 3;

    const float* Qb = (stream ? Qsv : Qp) + (size_t)nh * SDIM * DKH;
    const float* Kb = Kh + (size_t)nh * SDIM * DKH;
    const float* Vb = Vh + (size_t)nh * SDIM * DKH;

    // Q fragments for this warp's 16 rows (tf32), 8 k-steps
    uint32_t qf[8][4];
    {
        const float* q0p = Qb + (size_t)(q0 + wid * 16 + r) * DKH;
        const float* q8p = q0p + 8 * DKH;
        #pragma unroll
        for (int ks = 0; ks < 8; ks++) {
            qf[ks][0] = __float_as_uint(to_tf32(q0p[ks * 8 + cq]));
            qf[ks][1] = __float_as_uint(to_tf32(q8p[ks * 8 + cq]));
            qf[ks][2] = __float_as_uint(to_tf32(q0p[ks * 8 + cq + 4]));
            qf[ks][3] = __float_as_uint(to_tf32(q8p[ks * 8 + cq + 4]));
        }
    }

    float o[8][4];
    #pragma unroll
    for (int nt = 0; nt < 8; nt++)
        #pragma unroll
        for (int i = 0; i < 4; i++) o[nt][i] = 0.f;
    float m0v = -1e30f, m1v = -1e30f, l0 = 0.f, l1 = 0.f;

    for (int kt = 0; kt < SDIM / AKT; kt++) {
        const int k0 = kt * AKT;
        // ---- load K,V tiles (tf32), 8 float4 each per thread ----
        {
            const float4* ksrc = (const float4*)(Kb + (size_t)k0 * DKH);
            const float4* vsrc = (const float4*)(Vb + (size_t)k0 * DKH);
            #pragma unroll
            for (int i = 0; i < 8; i++) {
                const int idx = tid + 128 * i;     // 0..1023
                const int row = idx >> 4;
                const int c4  = (idx & 15) << 2;
                float4 kv = ksrc[idx];
                float4 vv = vsrc[idx];
                float4 k4, v4;
                k4.x = to_tf32(kv.x); k4.y = to_tf32(kv.y);
                k4.z = to_tf32(kv.z); k4.w = to_tf32(kv.w);
                v4.x = to_tf32(vv.x); v4.y = to_tf32(vv.y);
                v4.z = to_tf32(vv.z); v4.w = to_tf32(vv.w);
                *(float4*)(Ks + row * KS_STR + c4) = k4;
                *(float4*)(Vs + row * VS_STR + c4) = v4;
            }
            if (tid < AKT) madd[tid] = maddg[n * SDIM + k0 + tid];
        }
        __syncthreads();

        // ---- scores: S = Q @ K^T  (m16 x n64 x k64 per warp) ----
        float sc[8][4];
        #pragma unroll
        for (int nt = 0; nt < 8; nt++)
            #pragma unroll
            for (int i = 0; i < 4; i++) sc[nt][i] = 0.f;

        #pragma unroll
        for (int ks = 0; ks < 8; ks++) {
            const int kb = ks * 8;
            #pragma unroll
            for (int nt = 0; nt < 8; nt++) {
                uint32_t b[2];
                const float* p = Ks + (nt * 8 + r) * KS_STR + kb + cq;
                b[0] = __float_as_uint(p[0]);
                b[1] = __float_as_uint(p[4]);
                mma_tf32_16x8x8(sc[nt], qf[ks], b);
            }
        }

        // ---- softmax (rows r and r+8 of this warp's m16 tile) ----
        float tmax0 = -1e30f, tmax1 = -1e30f;
        #pragma unroll
        for (int nt = 0; nt < 8; nt++) {
            const int j = nt * 8 + 2 * cq;
            const float ma = madd[j], mb = madd[j + 1];
            sc[nt][0] = sc[nt][0] * 0.125f + ma;
            sc[nt][1] = sc[nt][1] * 0.125f + mb;
            sc[nt][2] = sc[nt][2] * 0.125f + ma;
            sc[nt][3] = sc[nt][3] * 0.125f + mb;
            tmax0 = fmaxf(tmax0, fmaxf(sc[nt][0], sc[nt][1]));
            tmax1 = fmaxf(tmax1, fmaxf(sc[nt][2], sc[nt][3]));
        }
        tmax0 = fmaxf(tmax0, __shfl_xor_sync(0xffffffffu, tmax0, 1));
        tmax0 = fmaxf(tmax0, __shfl_xor_sync(0xffffffffu, tmax0, 2));
        tmax1 = fmaxf(tmax1, __shfl_xor_sync(0xffffffffu, tmax1, 1));
        tmax1 = fmaxf(tmax1, __shfl_xor_sync(0xffffffffu, tmax1, 2));

        const float mn0 = fmaxf(m0v, tmax0);
        const float mn1 = fmaxf(m1v, tmax1);
        const float cr0 = __expf(m0v - mn0);
        const float cr1 = __expf(m1v - mn1);
        m0v = mn0; m1v = mn1;

        float ls0 = 0.f, ls1 = 0.f;
        float* prow0 = Ps + (wid * 16 + r) * PS_STR + 2 * cq;
        float* prow8 = prow0 + 8 * PS_STR;
        #pragma unroll
        for (int nt = 0; nt < 8; nt++) {
            const float p0 = __expf(sc[nt][0] - mn0);
            const float p1 = __expf(sc[nt][1] - mn0);
            const float p2 = __expf(sc[nt][2] - mn1);
            const float p3 = __expf(sc[nt][3] - mn1);
            ls0 += p0 + p1;
            ls1 += p2 + p3;
            float2 w0, w1;
            w0.x = to_tf32(p0); w0.y = to_tf32(p1);
            w1.x = to_tf32(p2); w1.y = to_tf32(p3);
            *(float2*)(prow0 + nt * 8) = w0;
            *(float2*)(prow8 + nt * 8) = w1;
            o[nt][0] *= cr0; o[nt][1] *= cr0;
            o[nt][2] *= cr1; o[nt][3] *= cr1;
        }
        ls0 += __shfl_xor_sync(0xffffffffu, ls0, 1);
        ls0 += __shfl_xor_sync(0xffffffffu, ls0, 2);
        ls1 += __shfl_xor_sync(0xffffffffu, ls1, 1);
        ls1 += __shfl_xor_sync(0xffffffffu, ls1, 2);
        l0 = l0 * cr0 + ls0;
        l1 = l1 * cr1 + ls1;

        __syncwarp();   // Ps rows are warp-private; just order STS->LDS

        // ---- O += P @ V  (m16 x n64(dk) x k64(keys)) ----
        #pragma unroll
        for (int ks = 0; ks < 8; ks++) {
            const int kb = ks * 8;
            uint32_t a[4];
            const float* pa = Ps + (wid * 16 + r) * PS_STR + kb;
            a[0] = __float_as_uint(pa[cq]);
            a[1] = __float_as_uint(pa[8 * PS_STR + cq]);
            a[2] = __float_as_uint(pa[cq + 4]);
            a[3] = __float_as_uint(pa[8 * PS_STR + cq + 4]);
            #pragma unroll
            for (int nt = 0; nt < 8; nt++) {
                uint32_t b[2];
                const float* pv = Vs + (kb + cq) * VS_STR + nt * 8 + r;
                b[0] = __float_as_uint(pv[0]);
                b[1] = __float_as_uint(pv[4 * VS_STR]);
                mma_tf32_16x8x8(o[nt], a, b);
            }
        }
        __syncthreads();   // before next tile overwrites Ks/Vs
    }

    // ---- epilogue ----
    const float inv0 = 1.f / l0;
    const float inv1 = 1.f / l1;
    const int h = nh % HH;
    const int q = q0 + wid * 16 + r;
    float* outp = (stream ? ctx1 : ctx0)
                + ((size_t)(n * SDIM + q)) * DDIM + h * DKH;
    float* outp8 = outp + 8 * DDIM;
    #pragma unroll
    for (int nt = 0; nt < 8; nt++) {
        const int dk = nt * 8 + 2 * cq;
        float2 v0, v1;
        v0.x = o[nt][0] * inv0; v0.y = o[nt][1] * inv0;
        v1.x = o[nt][2] * inv1; v1.y = o[nt][3] * inv1;
        *(float2*)(outp  + dk) = v0;
        *(float2*)(outp8 + dk) = v1;
    }
}

// ---------------------------------------------------------------------------
extern "C" void kernel_launch(void* const* d_in, const int* in_sizes, int n_in,
                              void* d_out, int out_size)
{
    const float* Qpoi = (const float*)d_in[0];
    const float* Qsvi = (const float*)d_in[1];
    const float* Kin  = (const float*)d_in[2];
    const float* Vin  = (const float*)d_in[3];
    const unsigned char* mask = (const unsigned char*)d_in[4];
    const float* wq_poi_w = (const float*)d_in[5];
    const float* wq_poi_b = (const float*)d_in[6];
    const float* wq_svi_w = (const float*)d_in[7];
    const float* wq_svi_b = (const float*)d_in[8];
    const float* wk_w = (const float*)d_in[9];
    const float* wk_b = (const float*)d_in[10];
    const float* wv_w = (const float*)d_in[11];
    const float* wv_b = (const float*)d_in[12];
    const float* fc_w = (const float*)d_in[13];
    const float* fc_b = (const float*)d_in[14];
    float* out = (float*)d_out;

    float *Qp, *Qs, *Kh, *Vh, *c0, *c1, *madd;
    cudaGetSymbolAddress((void**)&Qp, g_Qp);
    cudaGetSymbolAddress((void**)&Qs, g_Qs);
    cudaGetSymbolAddress((void**)&Kh, g_Kh);
    cudaGetSymbolAddress((void**)&Vh, g_Vh);
    cudaGetSymbolAddress((void**)&c0, g_ctx0);
    cudaGetSymbolAddress((void**)&c1, g_ctx1);
    cudaGetSymbolAddress((void**)&madd, g_madd);

    // 0) canonicalize padding mask
    mask_expand_kernel<<<1, 1024>>>(mask, madd);

    dim3 gg(DDIM / 128, (SDIM * NB) / 128);

    // 1) projections -> [N,H,S,DK]  (tensor cores, tf32)
    gemm_tc<0><<<gg, 256>>>(Qpoi, wq_poi_w, wq_poi_b, Qp);
    gemm_tc<0><<<gg, 256>>>(Qsvi, wq_svi_w, wq_svi_b, Qs);
    gemm_tc<0><<<gg, 256>>>(Kin,  wk_w,     wk_b,     Kh);
    gemm_tc<0><<<gg, 256>>>(Vin,  wv_w,     wv_b,     Vh);

    // 2) attention (tensor cores, tf32; both streams in z)
    const int smem = (AKT * KS_STR + AKT * VS_STR + AQT * PS_STR + AKT) * (int)sizeof(float);
    cudaFuncSetAttribute((const void*)attn_tc,
                         cudaFuncAttributeMaxDynamicSharedMemorySize, smem);
    attn_tc<<<dim3(SDIM / AQT, NB * HH, 2), 128, smem>>>(Qp, Qs, Kh, Vh, madd, c0, c1);

    // 3) output FC -> [S,N,D], poi then svi (tensor cores, tf32)
    gemm_tc<1><<<gg, 256>>>(c0, fc_w, fc_b, out);
    gemm_tc<1><<<gg, 256>>>(c1, fc_w, fc_b, out + (size_t)SDIM * NB * DDIM);
}

// round 5
// speedup vs baseline: 3.7067x; 1.1728x over previous
#include <cuda_runtime.h>
#include <cstdint>

// Problem dims
#define SDIM 1024
#define NB   8
#define DDIM 1024
#define HH   16
#define DKH  64

// ---------------- scratch (device globals; no allocations allowed) ----------
__device__ float g_Qp[(size_t)NB * HH * SDIM * DKH];   // [N,H,S,DK]
__device__ float g_Qs[(size_t)NB * HH * SDIM * DKH];
__device__ float g_Kh[(size_t)NB * HH * SDIM * DKH];
__device__ float g_Vh[(size_t)NB * HH * SDIM * DKH];
__device__ float g_ctx0[(size_t)NB * SDIM * DDIM];     // [N,S,D]
__device__ float g_ctx1[(size_t)NB * SDIM * DDIM];
__device__ float g_madd[(size_t)NB * SDIM];            // 0 or -1e9 additive mask

// ---------------- mask canonicalization -------------------------------------
__global__ void mask_expand_kernel(const unsigned char* __restrict__ m,
                                   float* __restrict__ madd)
{
    __shared__ int s_big, s_nonmult4, s_anynz;
    const int t = threadIdx.x;               // 1024 threads, single block
    if (t == 0) { s_big = 0; s_nonmult4 = 0; s_anynz = 0; }
    __syncthreads();

    const int total = NB * SDIM;             // 8192 entries
    int big = 0, nonm4 = 0, anynz = 0;
    for (int i = t; i < total; i += 1024) {
        unsigned char b = m[i];
        if (b > 1) big = 1;
        if (b) { anynz = 1; if (i & 3) nonm4 = 1; }
    }
    if (big)   atomicOr(&s_big, 1);
    if (nonm4) atomicOr(&s_nonmult4, 1);
    if (anynz) atomicOr(&s_anynz, 1);
    __syncthreads();

    const bool width4 = s_big || !s_nonmult4 || !s_anynz;

    for (int i = t; i < total; i += 1024) {
        unsigned char v;
        if (width4) {
            v = (unsigned char)(m[4 * i] | m[4 * i + 1] | m[4 * i + 2] | m[4 * i + 3]);
        } else {
            v = m[i];
        }
        madd[i] = v ? -1e9f : 0.f;
    }
}

// ---------------- tf32 mma helpers ------------------------------------------
__device__ __forceinline__ float to_tf32(float x) {
    float r;
    asm("cvt.rna.tf32.f32 %0, %1;" : "=f"(r) : "f"(x));
    return r;
}

__device__ __forceinline__ void mma_tf32_16x8x8(float* c, const uint32_t* a,
                                                const uint32_t* b)
{
    asm volatile(
        "mma.sync.aligned.m16n8k8.row.col.f32.tf32.tf32.f32 "
        "{%0,%1,%2,%3}, {%4,%5,%6,%7}, {%8,%9}, {%0,%1,%2,%3};"
        : "+f"(c[0]), "+f"(c[1]), "+f"(c[2]), "+f"(c[3])
        : "r"(a[0]), "r"(a[1]), "r"(a[2]), "r"(a[3]), "r"(b[0]), "r"(b[1]));
}

// ---------------- batched, pipelined tensor-core GEMM -----------------------
// C[m,dout] = sum_k A[m,k] * W[dout,k] + b[dout]; M=8192, N=K=1024.
// Block tile 128x128x16, 8 warps, warp tile 64x32; double-buffered smem with
// register prefetch -> one __syncthreads per K-step. blockIdx.z picks batch.
struct Batch4 {
    const float* A[4];
    const float* W[4];
    const float* bias[4];
    float* out[4];
};

template <int MODE>
__global__ void __launch_bounds__(256)
gemm_tc(Batch4 batch)
{
    constexpr int BM = 128, BN = 128, BK = 16, KD = 1024;
    constexpr int STR = 20;
    __shared__ float As[2][BM * STR];
    __shared__ float Bs[2][BN * STR];

    const int z = blockIdx.z;
    const float* __restrict__ A    = batch.A[z];
    const float* __restrict__ W    = batch.W[z];
    const float* __restrict__ bias = batch.bias[z];
    float* __restrict__ out        = batch.out[z];

    const int tid  = threadIdx.x;
    const int wid  = tid >> 5;
    const int lane = tid & 31;
    const int wm = wid & 1;
    const int wn = wid >> 1;
    const int m0 = blockIdx.y * BM;
    const int n0 = blockIdx.x * BN;

    const int r  = lane >> 2;
    const int cq = lane & 3;

    // per-thread load coordinates (2 float4 per operand)
    const int lrow0 = tid >> 2;
    const int lrow1 = (tid + 256) >> 2;
    const int lc4   = (tid & 3) << 2;

    const float* Aptr = A + (size_t)m0 * KD;
    const float* Wptr = W + (size_t)n0 * KD;

    float acc[4][4][4];
    #pragma unroll
    for (int mt = 0; mt < 4; mt++)
        #pragma unroll
        for (int nt = 0; nt < 4; nt++)
            #pragma unroll
            for (int i = 0; i < 4; i++) acc[mt][nt][i] = 0.f;

    float4 pa0, pa1, pb0, pb1;

    // prologue: load k0 = 0
    pa0 = *(const float4*)(Aptr + (size_t)lrow0 * KD + lc4);
    pa1 = *(const float4*)(Aptr + (size_t)lrow1 * KD + lc4);
    pb0 = *(const float4*)(Wptr + (size_t)lrow0 * KD + lc4);
    pb1 = *(const float4*)(Wptr + (size_t)lrow1 * KD + lc4);
    {
        float4 t;
        t.x = to_tf32(pa0.x); t.y = to_tf32(pa0.y); t.z = to_tf32(pa0.z); t.w = to_tf32(pa0.w);
        *(float4*)(As[0] + lrow0 * STR + lc4) = t;
        t.x = to_tf32(pa1.x); t.y = to_tf32(pa1.y); t.z = to_tf32(pa1.z); t.w = to_tf32(pa1.w);
        *(float4*)(As[0] + lrow1 * STR + lc4) = t;
        t.x = to_tf32(pb0.x); t.y = to_tf32(pb0.y); t.z = to_tf32(pb0.z); t.w = to_tf32(pb0.w);
        *(float4*)(Bs[0] + lrow0 * STR + lc4) = t;
        t.x = to_tf32(pb1.x); t.y = to_tf32(pb1.y); t.z = to_tf32(pb1.z); t.w = to_tf32(pb1.w);
        *(float4*)(Bs[0] + lrow1 * STR + lc4) = t;
    }
    __syncthreads();

    for (int it = 0; it < KD / BK; it++) {
        const int cur = it & 1;
        const int nxt = cur ^ 1;
        const bool more = (it + 1) < KD / BK;

        // prefetch next K-slab into registers (overlaps with mma below)
        if (more) {
            const int kn = (it + 1) * BK;
            pa0 = *(const float4*)(Aptr + (size_t)lrow0 * KD + kn + lc4);
            pa1 = *(const float4*)(Aptr + (size_t)lrow1 * KD + kn + lc4);
            pb0 = *(const float4*)(Wptr + (size_t)lrow0 * KD + kn + lc4);
            pb1 = *(const float4*)(Wptr + (size_t)lrow1 * KD + kn + lc4);
        }

        // compute on current stage
        const float* Asc = As[cur];
        const float* Bsc = Bs[cur];
        #pragma unroll
        for (int ks = 0; ks < 2; ks++) {
            const int kb = ks * 8;
            uint32_t af[4][4];
            #pragma unroll
            for (int mt = 0; mt < 4; mt++) {
                const int mrow = wm * 64 + mt * 16 + r;
                const float* p = Asc + mrow * STR + kb + cq;
                af[mt][0] = __float_as_uint(p[0]);
                af[mt][1] = __float_as_uint(p[8 * STR]);
                af[mt][2] = __float_as_uint(p[4]);
                af[mt][3] = __float_as_uint(p[8 * STR + 4]);
            }
            uint32_t bf[4][2];
            #pragma unroll
            for (int nt = 0; nt < 4; nt++) {
                const int nrow = wn * 32 + nt * 8 + r;
                const float* p = Bsc + nrow * STR + kb + cq;
                bf[nt][0] = __float_as_uint(p[0]);
                bf[nt][1] = __float_as_uint(p[4]);
            }
            #pragma unroll
            for (int mt = 0; mt < 4; mt++)
                #pragma unroll
                for (int nt = 0; nt < 4; nt++)
                    mma_tf32_16x8x8(acc[mt][nt], af[mt], bf[nt]);
        }

        // store prefetched slab into the other stage
        if (more) {
            float4 t;
            t.x = to_tf32(pa0.x); t.y = to_tf32(pa0.y); t.z = to_tf32(pa0.z); t.w = to_tf32(pa0.w);
            *(float4*)(As[nxt] + lrow0 * STR + lc4) = t;
            t.x = to_tf32(pa1.x); t.y = to_tf32(pa1.y); t.z = to_tf32(pa1.z); t.w = to_tf32(pa1.w);
            *(float4*)(As[nxt] + lrow1 * STR + lc4) = t;
            t.x = to_tf32(pb0.x); t.y = to_tf32(pb0.y); t.z = to_tf32(pb0.z); t.w = to_tf32(pb0.w);
            *(float4*)(Bs[nxt] + lrow0 * STR + lc4) = t;
            t.x = to_tf32(pb1.x); t.y = to_tf32(pb1.y); t.z = to_tf32(pb1.z); t.w = to_tf32(pb1.w);
            *(float4*)(Bs[nxt] + lrow1 * STR + lc4) = t;
        }
        __syncthreads();
    }

    // ---- epilogue: bias + scatter ----
    const int cpair = (lane & 3) * 2;
    #pragma unroll
    for (int nt = 0; nt < 4; nt++) {
        const int dout = n0 + wn * 32 + nt * 8 + cpair;
        const float2 bb = *(const float2*)(bias + dout);
        #pragma unroll
        for (int mt = 0; mt < 4; mt++) {
            #pragma unroll
            for (int half = 0; half < 2; half++) {
                const int m = m0 + wm * 64 + mt * 16 + r + half * 8;
                float2 v;
                v.x = acc[mt][nt][half * 2 + 0] + bb.x;
                v.y = acc[mt][nt][half * 2 + 1] + bb.y;
                if (MODE == 0) {
                    const int s = m >> 3, n = m & 7;
                    const int h = dout >> 6, dk = dout & 63;
                    *(float2*)(out + ((size_t)((n * HH + h) * SDIM + s)) * DKH + dk) = v;
                } else {
                    const int n = m >> 10, s = m & 1023;
                    *(float2*)(out + ((size_t)(s * NB + n)) * DDIM + dout) = v;
                }
            }
        }
    }
}

// ---------------- tensor-core flash attention --------------------------------
#define AQT 64
#define AKT 64
#define KS_STR 68
#define VS_STR 72
#define PS_STR 68

__global__ void __launch_bounds__(128)
attn_tc(const float* __restrict__ Qp, const float* __restrict__ Qsv,
        const float* __restrict__ Kh, const float* __restrict__ Vh,
        const float* __restrict__ maddg,
        float* __restrict__ ctx0, float* __restrict__ ctx1)
{
    extern __shared__ float sm[];
    float* Ks   = sm;                         // [64][KS_STR]
    float* Vs   = Ks + AKT * KS_STR;          // [64][VS_STR]
    float* Ps   = Vs + AKT * VS_STR;          // [64][PS_STR]
    float* madd = Ps + AQT * PS_STR;          // [64]

    const int nh = blockIdx.y;
    const int n  = nh / HH;
    const int stream = blockIdx.z;
    const int q0 = blockIdx.x * AQT;
    const int tid = threadIdx.x;
    const int wid = tid >> 5;
    const int lane = tid & 31;
    const int r  = lane >> 2;
    const int cq = lane & 3;

    const float* Qb = (stream ? Qsv : Qp) + (size_t)nh * SDIM * DKH;
    const float* Kb = Kh + (size_t)nh * SDIM * DKH;
    const float* Vb = Vh + (size_t)nh * SDIM * DKH;

    uint32_t qf[8][4];
    {
        const float* q0p = Qb + (size_t)(q0 + wid * 16 + r) * DKH;
        const float* q8p = q0p + 8 * DKH;
        #pragma unroll
        for (int ks = 0; ks < 8; ks++) {
            qf[ks][0] = __float_as_uint(to_tf32(q0p[ks * 8 + cq]));
            qf[ks][1] = __float_as_uint(to_tf32(q8p[ks * 8 + cq]));
            qf[ks][2] = __float_as_uint(to_tf32(q0p[ks * 8 + cq + 4]));
            qf[ks][3] = __float_as_uint(to_tf32(q8p[ks * 8 + cq + 4]));
        }
    }

    float o[8][4];
    #pragma unroll
    for (int nt = 0; nt < 8; nt++)
        #pragma unroll
        for (int i = 0; i < 4; i++) o[nt][i] = 0.f;
    float m0v = -1e30f, m1v = -1e30f, l0 = 0.f, l1 = 0.f;

    for (int kt = 0; kt < SDIM / AKT; kt++) {
        const int k0 = kt * AKT;
        {
            const float4* ksrc = (const float4*)(Kb + (size_t)k0 * DKH);
            const float4* vsrc = (const float4*)(Vb + (size_t)k0 * DKH);
            #pragma unroll
            for (int i = 0; i < 8; i++) {
                const int idx = tid + 128 * i;
                const int row = idx >> 4;
                const int c4  = (idx & 15) << 2;
                float4 kv = ksrc[idx];
                float4 vv = vsrc[idx];
                float4 k4, v4;
                k4.x = to_tf32(kv.x); k4.y = to_tf32(kv.y);
                k4.z = to_tf32(kv.z); k4.w = to_tf32(kv.w);
                v4.x = to_tf32(vv.x); v4.y = to_tf32(vv.y);
                v4.z = to_tf32(vv.z); v4.w = to_tf32(vv.w);
                *(float4*)(Ks + row * KS_STR + c4) = k4;
                *(float4*)(Vs + row * VS_STR + c4) = v4;
            }
            if (tid < AKT) madd[tid] = maddg[n * SDIM + k0 + tid];
        }
        __syncthreads();

        float sc[8][4];
        #pragma unroll
        for (int nt = 0; nt < 8; nt++)
            #pragma unroll
            for (int i = 0; i < 4; i++) sc[nt][i] = 0.f;

        #pragma unroll
        for (int ks = 0; ks < 8; ks++) {
            const int kb = ks * 8;
            #pragma unroll
            for (int nt = 0; nt < 8; nt++) {
                uint32_t b[2];
                const float* p = Ks + (nt * 8 + r) * KS_STR + kb + cq;
                b[0] = __float_as_uint(p[0]);
                b[1] = __float_as_uint(p[4]);
                mma_tf32_16x8x8(sc[nt], qf[ks], b);
            }
        }

        float tmax0 = -1e30f, tmax1 = -1e30f;
        #pragma unroll
        for (int nt = 0; nt < 8; nt++) {
            const int j = nt * 8 + 2 * cq;
            const float ma = madd[j], mb = madd[j + 1];
            sc[nt][0] = sc[nt][0] * 0.125f + ma;
            sc[nt][1] = sc[nt][1] * 0.125f + mb;
            sc[nt][2] = sc[nt][2] * 0.125f + ma;
            sc[nt][3] = sc[nt][3] * 0.125f + mb;
            tmax0 = fmaxf(tmax0, fmaxf(sc[nt][0], sc[nt][1]));
            tmax1 = fmaxf(tmax1, fmaxf(sc[nt][2], sc[nt][3]));
        }
        tmax0 = fmaxf(tmax0, __shfl_xor_sync(0xffffffffu, tmax0, 1));
        tmax0 = fmaxf(tmax0, __shfl_xor_sync(0xffffffffu, tmax0, 2));
        tmax1 = fmaxf(tmax1, __shfl_xor_sync(0xffffffffu, tmax1, 1));
        tmax1 = fmaxf(tmax1, __shfl_xor_sync(0xffffffffu, tmax1, 2));

        const float mn0 = fmaxf(m0v, tmax0);
        const float mn1 = fmaxf(m1v, tmax1);
        const float cr0 = __expf(m0v - mn0);
        const float cr1 = __expf(m1v - mn1);
        m0v = mn0; m1v = mn1;

        float ls0 = 0.f, ls1 = 0.f;
        float* prow0 = Ps + (wid * 16 + r) * PS_STR + 2 * cq;
        float* prow8 = prow0 + 8 * PS_STR;
        #pragma unroll
        for (int nt = 0; nt < 8; nt++) {
            const float p0 = __expf(sc[nt][0] - mn0);
            const float p1 = __expf(sc[nt][1] - mn0);
            const float p2 = __expf(sc[nt][2] - mn1);
            const float p3 = __expf(sc[nt][3] - mn1);
            ls0 += p0 + p1;
            ls1 += p2 + p3;
            float2 w0, w1;
            w0.x = to_tf32(p0); w0.y = to_tf32(p1);
            w1.x = to_tf32(p2); w1.y = to_tf32(p3);
            *(float2*)(prow0 + nt * 8) = w0;
            *(float2*)(prow8 + nt * 8) = w1;
            o[nt][0] *= cr0; o[nt][1] *= cr0;
            o[nt][2] *= cr1; o[nt][3] *= cr1;
        }
        ls0 += __shfl_xor_sync(0xffffffffu, ls0, 1);
        ls0 += __shfl_xor_sync(0xffffffffu, ls0, 2);
        ls1 += __shfl_xor_sync(0xffffffffu, ls1, 1);
        ls1 += __shfl_xor_sync(0xffffffffu, ls1, 2);
        l0 = l0 * cr0 + ls0;
        l1 = l1 * cr1 + ls1;

        __syncwarp();

        #pragma unroll
        for (int ks = 0; ks < 8; ks++) {
            const int kb = ks * 8;
            uint32_t a[4];
            const float* pa = Ps + (wid * 16 + r) * PS_STR + kb;
            a[0] = __float_as_uint(pa[cq]);
            a[1] = __float_as_uint(pa[8 * PS_STR + cq]);
            a[2] = __float_as_uint(pa[cq + 4]);
            a[3] = __float_as_uint(pa[8 * PS_STR + cq + 4]);
            #pragma unroll
            for (int nt = 0; nt < 8; nt++) {
                uint32_t b[2];
                const float* pv = Vs + (kb + cq) * VS_STR + nt * 8 + r;
                b[0] = __float_as_uint(pv[0]);
                b[1] = __float_as_uint(pv[4 * VS_STR]);
                mma_tf32_16x8x8(o[nt], a, b);
            }
        }
        __syncthreads();
    }

    const float inv0 = 1.f / l0;
    const float inv1 = 1.f / l1;
    const int h = nh % HH;
    const int q = q0 + wid * 16 + r;
    float* outp = (stream ? ctx1 : ctx0)
                + ((size_t)(n * SDIM + q)) * DDIM + h * DKH;
    float* outp8 = outp + 8 * DDIM;
    #pragma unroll
    for (int nt = 0; nt < 8; nt++) {
        const int dk = nt * 8 + 2 * cq;
        float2 v0, v1;
        v0.x = o[nt][0] * inv0; v0.y = o[nt][1] * inv0;
        v1.x = o[nt][2] * inv1; v1.y = o[nt][3] * inv1;
        *(float2*)(outp  + dk) = v0;
        *(float2*)(outp8 + dk) = v1;
    }
}

// ---------------------------------------------------------------------------
extern "C" void kernel_launch(void* const* d_in, const int* in_sizes, int n_in,
                              void* d_out, int out_size)
{
    const float* Qpoi = (const float*)d_in[0];
    const float* Qsvi = (const float*)d_in[1];
    const float* Kin  = (const float*)d_in[2];
    const float* Vin  = (const float*)d_in[3];
    const unsigned char* mask = (const unsigned char*)d_in[4];
    const float* wq_poi_w = (const float*)d_in[5];
    const float* wq_poi_b = (const float*)d_in[6];
    const float* wq_svi_w = (const float*)d_in[7];
    const float* wq_svi_b = (const float*)d_in[8];
    const float* wk_w = (const float*)d_in[9];
    const float* wk_b = (const float*)d_in[10];
    const float* wv_w = (const float*)d_in[11];
    const float* wv_b = (const float*)d_in[12];
    const float* fc_w = (const float*)d_in[13];
    const float* fc_b = (const float*)d_in[14];
    float* out = (float*)d_out;

    float *Qp, *Qs, *Kh, *Vh, *c0, *c1, *madd;
    cudaGetSymbolAddress((void**)&Qp, g_Qp);
    cudaGetSymbolAddress((void**)&Qs, g_Qs);
    cudaGetSymbolAddress((void**)&Kh, g_Kh);
    cudaGetSymbolAddress((void**)&Vh, g_Vh);
    cudaGetSymbolAddress((void**)&c0, g_ctx0);
    cudaGetSymbolAddress((void**)&c1, g_ctx1);
    cudaGetSymbolAddress((void**)&madd, g_madd);

    // 0) canonicalize padding mask
    mask_expand_kernel<<<1, 1024>>>(mask, madd);

    // 1) projections -> [N,H,S,DK] (one batched launch, z = 4)
    Batch4 proj;
    proj.A[0] = Qpoi;     proj.W[0] = wq_poi_w; proj.bias[0] = wq_poi_b; proj.out[0] = Qp;
    proj.A[1] = Qsvi;     proj.W[1] = wq_svi_w; proj.bias[1] = wq_svi_b; proj.out[1] = Qs;
    proj.A[2] = Kin;      proj.W[2] = wk_w;     proj.bias[2] = wk_b;     proj.out[2] = Kh;
    proj.A[3] = Vin;      proj.W[3] = wv_w;     proj.bias[3] = wv_b;     proj.out[3] = Vh;
    gemm_tc<0><<<dim3(DDIM / 128, (SDIM * NB) / 128, 4), 256>>>(proj);

    // 2) attention (tensor cores, tf32; both streams in z)
    const int smem = (AKT * KS_STR + AKT * VS_STR + AQT * PS_STR + AKT) * (int)sizeof(float);
    cudaFuncSetAttribute((const void*)attn_tc,
                         cudaFuncAttributeMaxDynamicSharedMemorySize, smem);
    attn_tc<<<dim3(SDIM / AQT, NB * HH, 2), 128, smem>>>(Qp, Qs, Kh, Vh, madd, c0, c1);

    // 3) output FC -> [S,N,D] (one batched launch, z = 2)
    Batch4 fc;
    fc.A[0] = c0; fc.W[0] = fc_w; fc.bias[0] = fc_b; fc.out[0] = out;
    fc.A[1] = c1; fc.W[1] = fc_w; fc.bias[1] = fc_b; fc.out[1] = out + (size_t)SDIM * NB * DDIM;
    fc.A[2] = c0; fc.W[2] = fc_w; fc.bias[2] = fc_b; fc.out[2] = out;  // unused
    fc.A[3] = c1; fc.W[3] = fc_w; fc.bias[3] = fc_b; fc.out[3] = out + (size_t)SDIM * NB * DDIM;  // unused
    gemm_tc<1><<<dim3(DDIM / 128, (SDIM * NB) / 128, 2), 256>>>(fc);
}